// round 13
// baseline (speedup 1.0000x reference)
#include <cuda_runtime.h>
#include <cstdint>

// Problem constants (from reference)
#define C_N0 200000
#define C_N1 50000
#define C_N2 10000
#define C_INF 128
#define C_HID 128
#define C_RANK 64
#define C_OUTC 64
#define C_E1 800000
#define C_E2 160000
#define PAD 128
#define NSM 148

// ---------------- scratch (device globals; no allocation) ----------------
__device__ int   g_cnt1 [C_N1];
__device__ __align__(16) int   g_adj1 [(size_t)C_N1 * PAD];
__device__ __align__(16) float g_h    [(size_t)C_N1 * C_HID];
__device__ int   g_cnt2 [C_N2];
__device__ __align__(16) int   g_adj2 [(size_t)C_N2 * PAD];

// fragment-major tf32 weight panels: [kstep][ntile][lane]{b0,b1}
__device__ __align__(16) float g_fS1[128 * 64];
__device__ __align__(16) float g_fD1[128 * 64];
__device__ __align__(16) float g_fO1[64 * 128];
__device__ __align__(16) float g_fS2[128 * 64];
__device__ __align__(16) float g_fD2[128 * 64];
__device__ __align__(16) float g_fO2[64 * 64];

// ---------------- helpers ----------------
__device__ __forceinline__ uint32_t smem_u32(const void* p) {
    uint32_t a;
    asm("{ .reg .u64 t; cvta.to.shared.u64 t, %1; cvt.u32.u64 %0, t; }" : "=r"(a) : "l"(p));
    return a;
}
__device__ __forceinline__ uint32_t f2tf32(float f) {
    uint32_t r;
    asm("cvt.rna.tf32.f32 %0, %1;" : "=r"(r) : "f"(f));
    return r;
}
__device__ __forceinline__ void mma_tf32(float* c, uint32_t a0, uint32_t a1,
                                         uint32_t a2, uint32_t a3,
                                         uint32_t b0, uint32_t b1) {
    asm volatile(
        "mma.sync.aligned.m16n8k8.row.col.f32.tf32.tf32.f32 "
        "{%0,%1,%2,%3}, {%4,%5,%6,%7}, {%8,%9}, {%0,%1,%2,%3};"
        : "+f"(c[0]), "+f"(c[1]), "+f"(c[2]), "+f"(c[3])
        : "r"(a0), "r"(a1), "r"(a2), "r"(a3), "r"(b0), "r"(b1));
}
__device__ __forceinline__ void cp16(uint32_t dst, const void* src, int sz) {
    asm volatile("cp.async.cg.shared.global [%0], [%1], 16, %2;"
                 :: "r"(dst), "l"(src), "r"(sz));
}

// ---------------- setup: weight frag prep + zero counters ----------------
__global__ void setup_kernel(const float* __restrict__ Ws1, const float* __restrict__ Wd1,
                             const float* __restrict__ Wo1, const float* __restrict__ Ws2,
                             const float* __restrict__ Wd2, const float* __restrict__ Wo2,
                             float* __restrict__ Fs1, float* __restrict__ Fd1,
                             float* __restrict__ Fo1, float* __restrict__ Fs2,
                             float* __restrict__ Fd2, float* __restrict__ Fo2,
                             int* __restrict__ cnt1, int* __restrict__ cnt2)
{
    int i = blockIdx.x * 256 + threadIdx.x;
    if (i < C_N1) cnt1[i] = 0;
    if (i < C_N2) cnt2[i] = 0;
    if (i >= 45056) return;
    const float* W; float* F; int N, idx;
    if      (i < 8192)  { W = Ws1; F = Fs1; N = 64;  idx = i; }
    else if (i < 16384) { W = Wd1; F = Fd1; N = 64;  idx = i - 8192; }
    else if (i < 24576) { W = Wo1; F = Fo1; N = 128; idx = i - 16384; }
    else if (i < 32768) { W = Ws2; F = Fs2; N = 64;  idx = i - 24576; }
    else if (i < 40960) { W = Wd2; F = Fd2; N = 64;  idx = i - 32768; }
    else                { W = Wo2; F = Fo2; N = 64;  idx = i - 40960; }
    int p    = idx & 1;
    int lane = (idx >> 1) & 31;
    int t    = idx >> 6;
    int NT   = N / 8;
    int nt   = t % NT;
    int kk   = t / NT;
    int k = kk * 8 + (lane & 3) + p * 4;
    int n = nt * 8 + (lane >> 2);
    F[idx] = __uint_as_float(f2tf32(W[k * N + n]));
}

// ---------------- padded adjacency fill ----------------------------------
__global__ void fill_pad(const int* __restrict__ src, const int* __restrict__ dst,
                         int* __restrict__ cnt, int* __restrict__ adj, int E)
{
    int e = blockIdx.x * blockDim.x + threadIdx.x;
    if (e >= E) return;
    int d = dst[e];
    int p = atomicAdd(&cnt[d], 1);
    if (p < PAD) adj[(size_t)d * PAD + p] = src[e];
}

// ---------------- producer: gather-mean one row into smem -----------------
__device__ __forceinline__ void gather_row(const float* __restrict__ feat,
                                           const int* __restrict__ adj,
                                           const int* __restrict__ cnt,
                                           float* __restrict__ dstRow,
                                           int grow, int M, int lane)
{
    float4 acc = make_float4(0.f, 0.f, 0.f, 0.f);
    float sc = 0.f;
    if (grow < M) {
        int cn = cnt[grow];
        int c  = min(cn, PAD);
        const int* ap = adj + (size_t)grow * PAD;
        int j = 0;
        for (; j + 7 < c; j += 8) {
            int s[8];
            #pragma unroll
            for (int u = 0; u < 8; u++) s[u] = __ldg(&ap[j + u]);
            #pragma unroll
            for (int u = 0; u < 8; u++) {
                float4 v = *(const float4*)&feat[(size_t)s[u] * 128 + lane * 4];
                acc.x += v.x; acc.y += v.y; acc.z += v.z; acc.w += v.w;
            }
        }
        for (; j < c; j++) {
            int s0 = __ldg(&ap[j]);
            float4 v = *(const float4*)&feat[(size_t)s0 * 128 + lane * 4];
            acc.x += v.x; acc.y += v.y; acc.z += v.z; acc.w += v.w;
        }
        sc = 1.0f / fmaxf((float)cn, 1.0f);
    }
    float4 v = make_float4(acc.x * sc, acc.y * sc, acc.z * sc, acc.w * sc);
    *(float4*)&dstRow[lane * 4] = v;
}

// ---------------- fused layer: gather + dual GEMM + out GEMM -------------
// C[M,NOUT] = act( ((mean_adj(feat) @ W1) * (feat @ W2)) @ WO + bias )
// 256 threads: warps 0-3 = consumers (R8-style 228-reg compute body,
// 16 rows each of the 64-row tile, all 8 rank-ntiles), warps 4-7 =
// producers (gather A1 rows + cp.async A2 for the NEXT tile, double-buffered).
template <int NOUT, bool RELU>
__global__ void __launch_bounds__(256, 1)
fused_layer(const float* __restrict__ feat,
            const int* __restrict__ adj, const int* __restrict__ cnt,
            const float* __restrict__ F1, const float* __restrict__ F2,
            const float* __restrict__ FO, const float* __restrict__ bias,
            float* __restrict__ C, int M)
{
    extern __shared__ float smem[];
    constexpr int KP   = 132;
    constexpr int KP2  = 68;
    constexpr int ABUF = 64 * KP;        // 8448 floats
    constexpr int NT   = 8;
    constexpr int KS   = 16;
    constexpr int NT2  = NOUT / 8;       // 16 or 8
    constexpr int NH   = NT2 / 8;        // 2 or 1

    float* As  = smem;                   // [2 bufs][A1,A2][ABUF]
    float* Bs1 = smem + 4 * ABUF;
    float* Bs2 = Bs1 + 8192;
    float* Zs  = Bs2 + 8192;             // 64*68

    const int tid   = threadIdx.x;
    const int wid   = tid >> 5;
    const int lane  = tid & 31;
    const bool prod = (wid >= 4);

    const uint32_t sAs = smem_u32(As);
    const uint32_t sB1 = smem_u32(Bs1);
    const uint32_t sB2 = smem_u32(Bs2);

    const int ntiles = (M + 63) >> 6;

    // ---- prologue: stage B panels (all), tile-0 A pair (producers) ----
    for (int i = tid; i < 2048; i += 256) cp16(sB1 + i * 16, (const char*)F1 + i * 16, 16);
    for (int i = tid; i < 2048; i += 256) cp16(sB2 + i * 16, (const char*)F2 + i * 16, 16);
    if (prod && (int)blockIdx.x < ntiles) {
        int ptid = tid - 128;            // 0..127
        int row0 = blockIdx.x * 64;
        #pragma unroll 2
        for (int i = ptid; i < 2048; i += 128) {
            int r = i >> 5, c = (i & 31) << 2;
            int gr = row0 + r;
            int sz = (gr < M) ? 16 : 0;
            cp16(sAs + (uint32_t)(ABUF + r * KP + c) * 4, &feat[(size_t)gr * 128 + c], sz);
        }
    }
    asm volatile("cp.async.commit_group;");
    if (prod && (int)blockIdx.x < ntiles) {
        int p = wid - 4;                 // 0..3
        int row0 = blockIdx.x * 64;
        for (int rr = 0; rr < 16; rr++) {
            int row = p * 16 + rr;
            gather_row(feat, adj, cnt, &As[row * KP], row0 + row, M, lane);
        }
    }
    asm volatile("cp.async.wait_group 0;");
    __syncthreads();                     // S1 (tile 0 ready)

    int buf = 0;
    const float2* bfo = (const float2*)FO;

    for (int t = blockIdx.x; t < ntiles; t += gridDim.x) {
        if (prod) {
            // ---- produce tile t+grid into buf^1 ----
            int tn = t + gridDim.x;
            int ptid = tid - 128;
            uint32_t base = sAs + (uint32_t)((buf ^ 1) * 2 * ABUF) * 4;
            float* a1n = As + (buf ^ 1) * 2 * ABUF;
            if (tn < ntiles) {
                int row0n = tn * 64;
                #pragma unroll 2
                for (int i = ptid; i < 2048; i += 128) {
                    int r = i >> 5, c = (i & 31) << 2;
                    int gr = row0n + r;
                    int sz = (gr < M) ? 16 : 0;
                    cp16(base + (uint32_t)(ABUF + r * KP + c) * 4, &feat[(size_t)gr * 128 + c], sz);
                }
            }
            asm volatile("cp.async.commit_group;");
            if (tn < ntiles) {
                int p = wid - 4;
                int row0n = tn * 64;
                for (int rr = 0; rr < 16; rr++) {
                    int row = p * 16 + rr;
                    gather_row(feat, adj, cnt, &a1n[row * KP], row0n + row, M, lane);
                }
            }
            asm volatile("cp.async.wait_group 0;");
        } else {
            // ---- consume tile t from buf ----
            const int mw  = wid * 16;
            const int g   = lane >> 2;
            const int tig = lane & 3;
            const float* a1b = As + buf * 2 * ABUF + (mw + g) * KP + tig;
            const float* a2b = a1b + ABUF;

            // phase 1: accA = A1 @ W1
            float accA[NT][4];
            #pragma unroll
            for (int nt = 0; nt < NT; nt++)
                { accA[nt][0] = accA[nt][1] = accA[nt][2] = accA[nt][3] = 0.f; }
            #pragma unroll
            for (int kk = 0; kk < KS; kk++) {
                uint32_t a0 = f2tf32(a1b[kk * 8 + 0]);
                uint32_t a2 = f2tf32(a1b[kk * 8 + 4]);
                uint32_t a1 = f2tf32(a1b[kk * 8 + 8 * KP]);
                uint32_t a3 = f2tf32(a1b[kk * 8 + 8 * KP + 4]);
                const float2* bf = (const float2*)Bs1 + (kk * NT) * 32 + lane;
                #pragma unroll
                for (int nt = 0; nt < NT; nt++) {
                    float2 b = bf[nt * 32];
                    mma_tf32(accA[nt], a0, a1, a2, a3,
                             __float_as_uint(b.x), __float_as_uint(b.y));
                }
            }
            // phase 2: accB = A2 @ W2
            float accB[NT][4];
            #pragma unroll
            for (int nt = 0; nt < NT; nt++)
                { accB[nt][0] = accB[nt][1] = accB[nt][2] = accB[nt][3] = 0.f; }
            #pragma unroll
            for (int kk = 0; kk < KS; kk++) {
                uint32_t a0 = f2tf32(a2b[kk * 8 + 0]);
                uint32_t a2 = f2tf32(a2b[kk * 8 + 4]);
                uint32_t a1 = f2tf32(a2b[kk * 8 + 8 * KP]);
                uint32_t a3 = f2tf32(a2b[kk * 8 + 8 * KP + 4]);
                const float2* bf = (const float2*)Bs2 + (kk * NT) * 32 + lane;
                #pragma unroll
                for (int nt = 0; nt < NT; nt++) {
                    float2 b = bf[nt * 32];
                    mma_tf32(accB[nt], a0, a1, a2, a3,
                             __float_as_uint(b.x), __float_as_uint(b.y));
                }
            }
            // z = accA * accB -> Zs (tf32 bits)
            {
                const int lr = mw + g;
                #pragma unroll
                for (int nt = 0; nt < NT; nt++) {
                    int col = nt * 8 + 2 * tig;
                    uint2 v0, v1;
                    v0.x = f2tf32(accA[nt][0] * accB[nt][0]);
                    v0.y = f2tf32(accA[nt][1] * accB[nt][1]);
                    v1.x = f2tf32(accA[nt][2] * accB[nt][2]);
                    v1.y = f2tf32(accA[nt][3] * accB[nt][3]);
                    *(uint2*)&Zs[lr * KP2 + col]       = v0;
                    *(uint2*)&Zs[(lr + 8) * KP2 + col] = v1;
                }
            }
            asm volatile("bar.sync 1, 128;" ::: "memory");   // consumers only

            // phase 3: (z @ WO + bias)
            const float* zb = Zs + (mw + g) * KP2 + tig;
            const int row0 = t * 64;
            const int r0 = row0 + mw + g;
            const int r1 = r0 + 8;
            #pragma unroll
            for (int nh = 0; nh < NH; nh++) {
                float acc2[8][4];
                #pragma unroll
                for (int j = 0; j < 8; j++)
                    { acc2[j][0] = acc2[j][1] = acc2[j][2] = acc2[j][3] = 0.f; }
                #pragma unroll
                for (int kk = 0; kk < 8; kk++) {
                    uint32_t a0 = __float_as_uint(zb[kk * 8 + 0]);
                    uint32_t a2 = __float_as_uint(zb[kk * 8 + 4]);
                    uint32_t a1 = __float_as_uint(zb[kk * 8 + 8 * KP2]);
                    uint32_t a3 = __float_as_uint(zb[kk * 8 + 8 * KP2 + 4]);
                    #pragma unroll
                    for (int j = 0; j < 8; j++) {
                        float2 b = __ldg(&bfo[(size_t)(kk * NT2 + nh * 8 + j) * 32 + lane]);
                        mma_tf32(acc2[j], a0, a1, a2, a3,
                                 __float_as_uint(b.x), __float_as_uint(b.y));
                    }
                }
                #pragma unroll
                for (int j = 0; j < 8; j++) {
                    int col = (nh * 8 + j) * 8 + 2 * tig;
                    float2 bb = *(const float2*)&bias[col];
                    float2 v0 = make_float2(acc2[j][0] + bb.x, acc2[j][1] + bb.y);
                    float2 v1 = make_float2(acc2[j][2] + bb.x, acc2[j][3] + bb.y);
                    if (RELU) {
                        v0.x = fmaxf(v0.x, 0.f); v0.y = fmaxf(v0.y, 0.f);
                        v1.x = fmaxf(v1.x, 0.f); v1.y = fmaxf(v1.y, 0.f);
                    }
                    if (r0 < M) *(float2*)&C[(size_t)r0 * NOUT + col] = v0;
                    if (r1 < M) *(float2*)&C[(size_t)r1 * NOUT + col] = v1;
                }
            }
        }
        __syncthreads();                 // S1 for next tile (all 8 warps)
        buf ^= 1;
    }
}

// ---------------- launch ----------------
extern "C" void kernel_launch(void* const* d_in, const int* in_sizes, int n_in,
                              void* d_out, int out_size)
{
    const float* x      = (const float*)d_in[0];
    const float* W_src1 = (const float*)d_in[1];
    const float* W_dst1 = (const float*)d_in[2];
    const float* W_out1 = (const float*)d_in[3];
    const float* b1     = (const float*)d_in[4];
    const float* W_src2 = (const float*)d_in[5];
    const float* W_dst2 = (const float*)d_in[6];
    const float* W_out2 = (const float*)d_in[7];
    const float* b2     = (const float*)d_in[8];
    const int*   src1   = (const int*)d_in[9];
    const int*   dst1   = (const int*)d_in[10];
    const int*   src2   = (const int*)d_in[11];
    const int*   dst2   = (const int*)d_in[12];
    const int E1 = in_sizes[9];
    const int E2 = in_sizes[11];

    int *cnt1, *adj1, *cnt2, *adj2;
    float *h;
    float *fS1, *fD1, *fO1, *fS2, *fD2, *fO2;
    cudaGetSymbolAddress((void**)&cnt1, g_cnt1);
    cudaGetSymbolAddress((void**)&adj1, g_adj1);
    cudaGetSymbolAddress((void**)&h,    g_h);
    cudaGetSymbolAddress((void**)&cnt2, g_cnt2);
    cudaGetSymbolAddress((void**)&adj2, g_adj2);
    cudaGetSymbolAddress((void**)&fS1,  g_fS1);
    cudaGetSymbolAddress((void**)&fD1,  g_fD1);
    cudaGetSymbolAddress((void**)&fO1,  g_fO1);
    cudaGetSymbolAddress((void**)&fS2,  g_fS2);
    cudaGetSymbolAddress((void**)&fD2,  g_fD2);
    cudaGetSymbolAddress((void**)&fO2,  g_fO2);

    float* out = (float*)d_out;

    // smem: A 4*8448 + B 2*8192 + z 64*68 floats = 218112 bytes
    constexpr int SM_FUSED = (4 * 64 * 132 + 2 * 8192 + 64 * 68) * 4;
    cudaFuncSetAttribute(fused_layer<128, true>, cudaFuncAttributeMaxDynamicSharedMemorySize, SM_FUSED);
    cudaFuncSetAttribute(fused_layer<64, false>, cudaFuncAttributeMaxDynamicSharedMemorySize, SM_FUSED);

    // 1. setup: frag prep + zero counters
    setup_kernel<<<(50000 + 255) / 256, 256>>>(W_src1, W_dst1, W_out1, W_src2, W_dst2, W_out2,
                                               fS1, fD1, fO1, fS2, fD2, fO2, cnt1, cnt2);
    // 2+3. adjacency fills (fill2 independent of layer 1)
    fill_pad<<<(E1 + 255) / 256, 256>>>(src1, dst1, cnt1, adj1, E1);
    fill_pad<<<(E2 + 255) / 256, 256>>>(src2, dst2, cnt2, adj2, E2);
    // 4. h = relu( ((mean_adj1(x)@Ws1)*(x@Wd1)) @ Wo1 + b1 )   [gather fused]
    fused_layer<128, true><<<NSM, 256, SM_FUSED>>>(x, adj1, cnt1, fS1, fD1, fO1, b1, h, C_N1);
    // 5. out = ((mean_adj2(h)@Ws2)*(h@Wd2)) @ Wo2 + b2          [gather fused]
    fused_layer<64, false><<<NSM, 256, SM_FUSED>>>(h, adj2, cnt2, fS2, fD2, fO2, b2, out, C_N2);
}

// round 14
// speedup vs baseline: 3.0988x; 3.0988x over previous
#include <cuda_runtime.h>
#include <cstdint>

// Problem constants (from reference)
#define C_N0 200000
#define C_N1 50000
#define C_N2 10000
#define C_INF 128
#define C_HID 128
#define C_RANK 64
#define C_OUTC 64
#define C_E1 800000
#define C_E2 160000
#define PAD 128

// ---------------- scratch (device globals; no allocation) ----------------
__device__ int   g_cnt1 [C_N1];
__device__ __align__(16) int   g_adj1 [(size_t)C_N1 * PAD];
__device__ __align__(16) float g_aggx1[(size_t)C_N1 * C_INF];
__device__ __align__(16) float g_h    [(size_t)C_N1 * C_HID];
__device__ int   g_cnt2 [C_N2];
__device__ __align__(16) int   g_adj2 [(size_t)C_N2 * PAD];
__device__ __align__(16) float g_aggh2[(size_t)C_N2 * C_HID];

// fragment-major tf32 weight panels: [kstep][ntile][lane]{b0,b1}
__device__ __align__(16) float g_fS1[128 * 64];
__device__ __align__(16) float g_fD1[128 * 64];
__device__ __align__(16) float g_fO1[64 * 128];
__device__ __align__(16) float g_fS2[128 * 64];
__device__ __align__(16) float g_fD2[128 * 64];
__device__ __align__(16) float g_fO2[64 * 64];

// ---------------- helpers ----------------
__device__ __forceinline__ uint32_t smem_u32(const void* p) {
    uint32_t a;
    asm("{ .reg .u64 t; cvta.to.shared.u64 t, %1; cvt.u32.u64 %0, t; }" : "=r"(a) : "l"(p));
    return a;
}
__device__ __forceinline__ uint32_t f2tf32(float f) {
    uint32_t r;
    asm("cvt.rna.tf32.f32 %0, %1;" : "=r"(r) : "f"(f));
    return r;
}
__device__ __forceinline__ void mma_tf32(float* c, uint32_t a0, uint32_t a1,
                                         uint32_t a2, uint32_t a3,
                                         uint32_t b0, uint32_t b1) {
    asm volatile(
        "mma.sync.aligned.m16n8k8.row.col.f32.tf32.tf32.f32 "
        "{%0,%1,%2,%3}, {%4,%5,%6,%7}, {%8,%9}, {%0,%1,%2,%3};"
        : "+f"(c[0]), "+f"(c[1]), "+f"(c[2]), "+f"(c[3])
        : "r"(a0), "r"(a1), "r"(a2), "r"(a3), "r"(b0), "r"(b1));
}
__device__ __forceinline__ void cp16(uint32_t dst, const void* src, int sz) {
    asm volatile("cp.async.cg.shared.global [%0], [%1], 16, %2;"
                 :: "r"(dst), "l"(src), "r"(sz));
}
__device__ __forceinline__ void cp_commit_wait() {
    asm volatile("cp.async.commit_group;");
    asm volatile("cp.async.wait_group 0;");
}

// ---------------- setup: weight frag prep + zero counters ----------------
__global__ void setup_kernel(const float* __restrict__ Ws1, const float* __restrict__ Wd1,
                             const float* __restrict__ Wo1, const float* __restrict__ Ws2,
                             const float* __restrict__ Wd2, const float* __restrict__ Wo2,
                             float* __restrict__ Fs1, float* __restrict__ Fd1,
                             float* __restrict__ Fo1, float* __restrict__ Fs2,
                             float* __restrict__ Fd2, float* __restrict__ Fo2,
                             int* __restrict__ cnt1, int* __restrict__ cnt2)
{
    int i = blockIdx.x * 256 + threadIdx.x;
    if (i < C_N1) cnt1[i] = 0;
    if (i < C_N2) cnt2[i] = 0;
    if (i >= 45056) return;
    const float* W; float* F; int N, idx;
    if      (i < 8192)  { W = Ws1; F = Fs1; N = 64;  idx = i; }
    else if (i < 16384) { W = Wd1; F = Fd1; N = 64;  idx = i - 8192; }
    else if (i < 24576) { W = Wo1; F = Fo1; N = 128; idx = i - 16384; }
    else if (i < 32768) { W = Ws2; F = Fs2; N = 64;  idx = i - 24576; }
    else if (i < 40960) { W = Wd2; F = Fd2; N = 64;  idx = i - 32768; }
    else                { W = Wo2; F = Fo2; N = 64;  idx = i - 40960; }
    int p    = idx & 1;
    int lane = (idx >> 1) & 31;
    int t    = idx >> 6;
    int NT   = N / 8;
    int nt   = t % NT;
    int kk   = t / NT;
    int k = kk * 8 + (lane & 3) + p * 4;
    int n = nt * 8 + (lane >> 2);
    F[idx] = __uint_as_float(f2tf32(W[k * N + n]));
}

// ---------------- padded adjacency fill ----------------------------------
__global__ void fill_pad(const int* __restrict__ src, const int* __restrict__ dst,
                         int* __restrict__ cnt, int* __restrict__ adj, int E)
{
    int e = blockIdx.x * blockDim.x + threadIdx.x;
    if (e >= E) return;
    int d = dst[e];
    int p = atomicAdd(&cnt[d], 1);
    if (p < PAD) adj[(size_t)d * PAD + p] = src[e];
}

// ---------------- gather-mean over 128-dim features (8-deep MLP) ---------
__global__ void gather_mean128(const float* __restrict__ feat,
                               const int* __restrict__ adj,
                               const int* __restrict__ cnt,
                               float* __restrict__ out, int Ndst)
{
    int warp = (blockIdx.x * blockDim.x + threadIdx.x) >> 5;
    int lane = threadIdx.x & 31;
    if (warp >= Ndst) return;
    const int* ap = &adj[(size_t)warp * PAD];
    int cn = cnt[warp];
    int c  = min(cn, PAD);
    float4 acc = make_float4(0.f, 0.f, 0.f, 0.f);
    int j = 0;
    for (; j + 7 < c; j += 8) {
        int s[8];
        #pragma unroll
        for (int u = 0; u < 8; u++) s[u] = __ldg(&ap[j + u]);
        float4 v[8];
        #pragma unroll
        for (int u = 0; u < 8; u++)
            v[u] = *(const float4*)&feat[(size_t)s[u] * 128 + lane * 4];
        #pragma unroll
        for (int u = 0; u < 8; u++) {
            acc.x += v[u].x; acc.y += v[u].y; acc.z += v[u].z; acc.w += v[u].w;
        }
    }
    for (; j + 3 < c; j += 4) {
        int s[4];
        #pragma unroll
        for (int u = 0; u < 4; u++) s[u] = __ldg(&ap[j + u]);
        #pragma unroll
        for (int u = 0; u < 4; u++) {
            float4 v = *(const float4*)&feat[(size_t)s[u] * 128 + lane * 4];
            acc.x += v.x; acc.y += v.y; acc.z += v.z; acc.w += v.w;
        }
    }
    for (; j < c; j++) {
        int s0 = __ldg(&ap[j]);
        float4 a = *(const float4*)&feat[(size_t)s0 * 128 + lane * 4];
        acc.x += a.x; acc.y += a.y; acc.z += a.z; acc.w += a.w;
    }
    float sc = 1.0f / fmaxf((float)cn, 1.0f);
    float4 v = make_float4(acc.x * sc, acc.y * sc, acc.z * sc, acc.w * sc);
    *(float4*)&out[(size_t)warp * 128 + lane * 4] = v;
}

// ---------------- fused layer GEMM, rank-split across warp pairs ----------
// C[M,NOUT] = act( ((A1@W1) * (A2@W2)) @ WO + bias ) ; K=128, rank 64.
// CTA: 256 threads = 8 warps. Warp (rw, h): rw = wid&3 -> rows [rw*16,+16),
// h = wid>>2 -> rank ntiles [h*4, h*4+4) (phases 1/2) and out ntiles
// [h*NJ, +NJ) (phase 3). Halved accumulators -> ~120 regs -> 2 CTAs/SM
// with 16 warps/SM (2x R8). Same smem layout / sync structure as R8.
template <int NOUT, bool RELU>
__global__ void __launch_bounds__(256, 2)
fused_layer(const float* __restrict__ A1, const float* __restrict__ A2,
            const float* __restrict__ F1, const float* __restrict__ F2,
            const float* __restrict__ FO, const float* __restrict__ bias,
            float* __restrict__ C, int M)
{
    extern __shared__ float smem[];
    constexpr int KP  = 132;            // pad 4 -> conflict-free A frags
    constexpr int KP2 = 68;
    constexpr int NT  = 8;              // rank 64 / 8
    constexpr int KS  = 16;             // 128 / 8
    constexpr int NT2 = NOUT / 8;       // 16 or 8
    constexpr int NJ  = NT2 / 2;        // per-warp phase-3 ntiles (8 or 4)

    float* As  = smem;                  // 64*132 floats (raw fp32 A; z reuse 64*68)
    float* Bs1 = smem + 64 * KP;        // 8192 floats
    float* Bs2 = Bs1 + 8192;            // 8192 floats

    const int tid  = threadIdx.x;
    const int wid  = tid >> 5;
    const int lane = tid & 31;
    const int g    = lane >> 2;
    const int tig  = lane & 3;
    const int rw   = wid & 3;           // row group
    const int h    = wid >> 2;          // rank half
    const int mw   = rw * 16;
    const int row0 = blockIdx.x * 64;

    const uint32_t sA  = smem_u32(As);
    const uint32_t sB1 = smem_u32(Bs1);
    const uint32_t sB2 = smem_u32(Bs2);

    // ---- async copies: B1, B2 panels + A1 tile (single group) ----
    for (int i = tid; i < 2048; i += 256) cp16(sB1 + i * 16, (const char*)F1 + i * 16, 16);
    for (int i = tid; i < 2048; i += 256) cp16(sB2 + i * 16, (const char*)F2 + i * 16, 16);
    for (int i = tid; i < 2048; i += 256) {
        int r = i >> 5;
        int c = (i & 31) << 2;
        int gr = row0 + r;
        int sz = (gr < M) ? 16 : 0;
        cp16(sA + (uint32_t)(r * KP + c) * 4, &A1[(size_t)gr * 128 + c], sz);
    }
    cp_commit_wait();
    __syncthreads();

    const float* abase = &As[(mw + g) * KP + tig];

    // ---- phase 1: accA = A1 @ W1 (ntiles h*4 .. h*4+3) ----
    float accA[4][4] = {};
    #pragma unroll
    for (int kk = 0; kk < KS; kk++) {
        uint32_t a0 = f2tf32(abase[kk * 8 + 0]);
        uint32_t a2 = f2tf32(abase[kk * 8 + 4]);
        uint32_t a1 = f2tf32(abase[kk * 8 + 8 * KP]);
        uint32_t a3 = f2tf32(abase[kk * 8 + 8 * KP + 4]);
        const float2* bf = (const float2*)Bs1 + (kk * NT + h * 4) * 32 + lane;
        #pragma unroll
        for (int j = 0; j < 4; j++) {
            float2 b = bf[j * 32];
            mma_tf32(accA[j], a0, a1, a2, a3,
                     __float_as_uint(b.x), __float_as_uint(b.y));
        }
    }
    __syncthreads();

    // ---- stage A2 (raw fp32, cp.async) ----
    for (int i = tid; i < 2048; i += 256) {
        int r = i >> 5;
        int c = (i & 31) << 2;
        int gr = row0 + r;
        int sz = (gr < M) ? 16 : 0;
        cp16(sA + (uint32_t)(r * KP + c) * 4, &A2[(size_t)gr * 128 + c], sz);
    }
    cp_commit_wait();
    __syncthreads();

    // ---- phase 2: accB = A2 @ W2 ----
    float accB[4][4] = {};
    #pragma unroll
    for (int kk = 0; kk < KS; kk++) {
        uint32_t a0 = f2tf32(abase[kk * 8 + 0]);
        uint32_t a2 = f2tf32(abase[kk * 8 + 4]);
        uint32_t a1 = f2tf32(abase[kk * 8 + 8 * KP]);
        uint32_t a3 = f2tf32(abase[kk * 8 + 8 * KP + 4]);
        const float2* bf = (const float2*)Bs2 + (kk * NT + h * 4) * 32 + lane;
        #pragma unroll
        for (int j = 0; j < 4; j++) {
            float2 b = bf[j * 32];
            mma_tf32(accB[j], a0, a1, a2, a3,
                     __float_as_uint(b.x), __float_as_uint(b.y));
        }
    }
    __syncthreads();   // all warps done reading A2 before z overwrites As

    // ---- z = accA * accB -> smem (tf32, padded KP2) ----
    {
        const int lr = mw + g;
        #pragma unroll
        for (int j = 0; j < 4; j++) {
            int col = (h * 4 + j) * 8 + 2 * tig;
            uint2 v0, v1;
            v0.x = f2tf32(accA[j][0] * accB[j][0]);
            v0.y = f2tf32(accA[j][1] * accB[j][1]);
            v1.x = f2tf32(accA[j][2] * accB[j][2]);
            v1.y = f2tf32(accA[j][3] * accB[j][3]);
            *(uint2*)&As[lr * KP2 + col]       = v0;
            *(uint2*)&As[(lr + 8) * KP2 + col] = v1;
        }
    }
    __syncthreads();

    // ---- phase 3: (z @ WO + bias), K=64, per-warp NJ ntiles ----
    const float* zb = &As[(mw + g) * KP2 + tig];
    const float2* bfo = (const float2*)FO;
    const int r0 = row0 + mw + g;
    const int r1 = r0 + 8;

    float acc2[NJ][4];
    #pragma unroll
    for (int j = 0; j < NJ; j++)
        { acc2[j][0] = acc2[j][1] = acc2[j][2] = acc2[j][3] = 0.f; }
    #pragma unroll
    for (int kk = 0; kk < 8; kk++) {
        uint32_t a0 = __float_as_uint(zb[kk * 8 + 0]);
        uint32_t a2 = __float_as_uint(zb[kk * 8 + 4]);
        uint32_t a1 = __float_as_uint(zb[kk * 8 + 8 * KP2]);
        uint32_t a3 = __float_as_uint(zb[kk * 8 + 8 * KP2 + 4]);
        #pragma unroll
        for (int j = 0; j < NJ; j++) {
            float2 b = __ldg(&bfo[(size_t)(kk * NT2 + h * NJ + j) * 32 + lane]);
            mma_tf32(acc2[j], a0, a1, a2, a3,
                     __float_as_uint(b.x), __float_as_uint(b.y));
        }
    }
    #pragma unroll
    for (int j = 0; j < NJ; j++) {
        int col = (h * NJ + j) * 8 + 2 * tig;
        float2 bb = *(const float2*)&bias[col];
        float2 v0 = make_float2(acc2[j][0] + bb.x, acc2[j][1] + bb.y);
        float2 v1 = make_float2(acc2[j][2] + bb.x, acc2[j][3] + bb.y);
        if (RELU) {
            v0.x = fmaxf(v0.x, 0.f); v0.y = fmaxf(v0.y, 0.f);
            v1.x = fmaxf(v1.x, 0.f); v1.y = fmaxf(v1.y, 0.f);
        }
        if (r0 < M) *(float2*)&C[(size_t)r0 * NOUT + col] = v0;
        if (r1 < M) *(float2*)&C[(size_t)r1 * NOUT + col] = v1;
    }
}

// ---------------- launch ----------------
extern "C" void kernel_launch(void* const* d_in, const int* in_sizes, int n_in,
                              void* d_out, int out_size)
{
    const float* x      = (const float*)d_in[0];
    const float* W_src1 = (const float*)d_in[1];
    const float* W_dst1 = (const float*)d_in[2];
    const float* W_out1 = (const float*)d_in[3];
    const float* b1     = (const float*)d_in[4];
    const float* W_src2 = (const float*)d_in[5];
    const float* W_dst2 = (const float*)d_in[6];
    const float* W_out2 = (const float*)d_in[7];
    const float* b2     = (const float*)d_in[8];
    const int*   src1   = (const int*)d_in[9];
    const int*   dst1   = (const int*)d_in[10];
    const int*   src2   = (const int*)d_in[11];
    const int*   dst2   = (const int*)d_in[12];
    const int E1 = in_sizes[9];
    const int E2 = in_sizes[11];

    int *cnt1, *adj1, *cnt2, *adj2;
    float *aggx1, *h, *aggh2;
    float *fS1, *fD1, *fO1, *fS2, *fD2, *fO2;
    cudaGetSymbolAddress((void**)&cnt1,  g_cnt1);
    cudaGetSymbolAddress((void**)&adj1,  g_adj1);
    cudaGetSymbolAddress((void**)&aggx1, g_aggx1);
    cudaGetSymbolAddress((void**)&h,     g_h);
    cudaGetSymbolAddress((void**)&cnt2,  g_cnt2);
    cudaGetSymbolAddress((void**)&adj2,  g_adj2);
    cudaGetSymbolAddress((void**)&aggh2, g_aggh2);
    cudaGetSymbolAddress((void**)&fS1,   g_fS1);
    cudaGetSymbolAddress((void**)&fD1,   g_fD1);
    cudaGetSymbolAddress((void**)&fO1,   g_fO1);
    cudaGetSymbolAddress((void**)&fS2,   g_fS2);
    cudaGetSymbolAddress((void**)&fD2,   g_fD2);
    cudaGetSymbolAddress((void**)&fO2,   g_fO2);

    float* out = (float*)d_out;

    // smem: A 64*132*4 + B1 32768 + B2 32768 = 99328 bytes -> 2 CTAs/SM
    constexpr int SM_FUSED = 64 * 132 * 4 + 2 * 32768;
    cudaFuncSetAttribute(fused_layer<128, true>, cudaFuncAttributeMaxDynamicSharedMemorySize, SM_FUSED);
    cudaFuncSetAttribute(fused_layer<64, false>, cudaFuncAttributeMaxDynamicSharedMemorySize, SM_FUSED);

    // 1. setup: frag prep + zero counters
    setup_kernel<<<(50000 + 255) / 256, 256>>>(W_src1, W_dst1, W_out1, W_src2, W_dst2, W_out2,
                                               fS1, fD1, fO1, fS2, fD2, fO2, cnt1, cnt2);
    // 2. layer-1 adjacency
    fill_pad<<<(E1 + 255) / 256, 256>>>(src1, dst1, cnt1, adj1, E1);
    // 3. layer-2 adjacency (independent of layer-1 compute; fill early)
    fill_pad<<<(E2 + 255) / 256, 256>>>(src2, dst2, cnt2, adj2, E2);
    // 4. aggx1 = segment_mean(x)
    gather_mean128<<<(C_N1 * 32 + 255) / 256, 256>>>(x, adj1, cnt1, aggx1, C_N1);
    // 5. h = relu( ((aggx1@Ws1)*(x@Wd1)) @ Wo1 + b1 )
    fused_layer<128, true><<<(C_N1 + 63) / 64, 256, SM_FUSED>>>(aggx1, x, fS1, fD1, fO1, b1, h, C_N1);
    // 6. aggh2 = segment_mean(h)
    gather_mean128<<<(C_N2 * 32 + 255) / 256, 256>>>(h, adj2, cnt2, aggh2, C_N2);
    // 7. out = ((aggh2@Ws2)*(h@Wd2)) @ Wo2 + b2
    fused_layer<64, false><<<(C_N2 + 63) / 64, 256, SM_FUSED>>>(aggh2, h, fS2, fD2, fO2, b2, out, C_N2);
}